// round 9
// baseline (speedup 1.0000x reference)
#include <cuda_runtime.h>

#define W 8192

static __device__ __align__(16) float g_bufA[8 * 32 * W];
static __device__ __align__(16) float g_bufB[8 * 32 * W];
static __device__ __align__(16) float g_h[8 * 256 * 4096];

// ---- packed f32x2 helpers (sm_103a FFMA2 path) ----------------------------
__device__ __forceinline__ unsigned long long ffma2(
    unsigned long long a, unsigned long long b, unsigned long long c)
{
    unsigned long long d;
    asm("fma.rn.f32x2 %0, %1, %2, %3;" : "=l"(d) : "l"(a), "l"(b), "l"(c));
    return d;
}
__device__ __forceinline__ unsigned long long pack2(float lo, float hi)
{
    unsigned long long r;
    asm("mov.b64 %0, {%1, %2};" : "=l"(r) : "f"(lo), "f"(hi));
    return r;
}
__device__ __forceinline__ float2 unpack2(unsigned long long v)
{
    float2 r;
    asm("mov.b64 {%0, %1}, %2;" : "=f"(r.x), "=f"(r.y) : "l"(v));
    return r;
}

// ---------------------------------------------------------------------------
// Start conv: bufA[b,c,ti] = sum_k start_w[c,k] * x_input[b,k,8192+ti]
// ---------------------------------------------------------------------------
__global__ __launch_bounds__(128) void start_kernel(
    const float* __restrict__ x_input, const float* __restrict__ start_w)
{
    __shared__ __align__(16) float wsm[32 * 256];  // [c][k]
    const int b = blockIdx.y;
    for (int i = threadIdx.x; i < 32 * 256; i += 128) wsm[i] = start_w[i];
    __syncthreads();

    const int ti = (blockIdx.x * 128 + threadIdx.x) * 2;
    const float* xb = x_input + (size_t)b * 256 * 16384 + 8192 + ti;

    float2 acc[32];
#pragma unroll
    for (int c = 0; c < 32; c++) acc[c] = make_float2(0.f, 0.f);

    const float4* wv = (const float4*)wsm;
#pragma unroll 4
    for (int k4 = 0; k4 < 64; k4++) {
        float2 x0 = *(const float2*)(xb + (size_t)(k4 * 4 + 0) * 16384);
        float2 x1 = *(const float2*)(xb + (size_t)(k4 * 4 + 1) * 16384);
        float2 x2 = *(const float2*)(xb + (size_t)(k4 * 4 + 2) * 16384);
        float2 x3 = *(const float2*)(xb + (size_t)(k4 * 4 + 3) * 16384);
#pragma unroll
        for (int c = 0; c < 32; c++) {
            float4 w = wv[c * 64 + k4];
            acc[c].x = fmaf(w.x, x0.x, acc[c].x);
            acc[c].y = fmaf(w.x, x0.y, acc[c].y);
            acc[c].x = fmaf(w.y, x1.x, acc[c].x);
            acc[c].y = fmaf(w.y, x1.y, acc[c].y);
            acc[c].x = fmaf(w.z, x2.x, acc[c].x);
            acc[c].y = fmaf(w.z, x2.y, acc[c].y);
            acc[c].x = fmaf(w.w, x3.x, acc[c].x);
            acc[c].y = fmaf(w.w, x3.y, acc[c].y);
        }
    }
#pragma unroll
    for (int c = 0; c < 32; c++)
        *(float2*)(&g_bufA[((size_t)b * 32 + c) * W + ti]) = acc[c];
}

// ---------------------------------------------------------------------------
// One WaveNet layer, lane-pair split: even lane = input channels 0..15,
// odd lane = 16..31. Partial gated sums combined via shfl_xor(1).
// 64 positions per 128-thread block -> 2x grid, ~95 regs -> 5 blocks/SM.
// ---------------------------------------------------------------------------
__global__ __launch_bounds__(128, 5) void layer_kernel(
    const float* __restrict__ filt, const float* __restrict__ gate,
    const float* __restrict__ resid, int d, int tstart, int dir, int last)
{
    __shared__ __align__(16) float sF[2048], sG[2048], sR[1024];
    {
        const float4* f4 = (const float4*)filt;
        const float4* g4 = (const float4*)gate;
        const float4* r4 = (const float4*)resid;
        float4* sF4 = (float4*)sF;
        float4* sG4 = (float4*)sG;
        float4* sR4 = (float4*)sR;
        for (int i = threadIdx.x; i < 512; i += 128) { sF4[i] = f4[i]; sG4[i] = g4[i]; }
        for (int i = threadIdx.x; i < 256; i += 128) sR4[i] = r4[i];
    }
    __syncthreads();

    const float* xin  = dir ? g_bufB : g_bufA;
    float*       xout = dir ? g_bufA : g_bufB;

    const int half   = threadIdx.x & 1;
    const int half16 = half << 4;
    int ti = tstart + blockIdx.x * 64 + (threadIdx.x >> 1);
    if (ti >= W) return;
    const unsigned mask = __activemask();

    const float* xb = xin + (size_t)blockIdx.y * 32 * W + ti;

    // 16 input channels for this lane: (prev, cur) packed
    unsigned long long cp[16];
#pragma unroll
    for (int r = 0; r < 16; r++) {
        const float* xr = xb + (half16 + r) * W;
        cp[r] = pack2(xr[-d], xr[0]);
    }

    float z[32];
#pragma unroll
    for (int c = 0; c < 32; c++) {
        const ulonglong2* fv = (const ulonglong2*)(sF + c * 64 + half * 32);
        const ulonglong2* gv = (const ulonglong2*)(sG + c * 64 + half * 32);
        unsigned long long af0 = 0, af1 = 0, ag0 = 0, ag1 = 0;
#pragma unroll
        for (int j = 0; j < 8; j++) {
            ulonglong2 wf = fv[j];
            ulonglong2 wg = gv[j];
            af0 = ffma2(wf.x, cp[2 * j],     af0);
            af1 = ffma2(wf.y, cp[2 * j + 1], af1);
            ag0 = ffma2(wg.x, cp[2 * j],     ag0);
            ag1 = ffma2(wg.y, cp[2 * j + 1], ag1);
        }
        float2 a0 = unpack2(af0), a1 = unpack2(af1);
        float2 g0 = unpack2(ag0), g1 = unpack2(ag1);
        float pa = (a0.x + a0.y) + (a1.x + a1.y);
        float pg = (g0.x + g0.y) + (g1.x + g1.y);
        pa += __shfl_xor_sync(mask, pa, 1);
        pg += __shfl_xor_sync(mask, pg, 1);
        // tanh(pa)*sigmoid(pg) = (e^{2a}-1) / ((e^{2a}+1)(1+e^{-g}))
        float e2a = __expf(2.f * pa);
        float eng = __expf(-pg);
        z[c] = __fdividef(e2a - 1.f, (e2a + 1.f) * (1.f + eng));
    }

    float* ob = xout + (size_t)blockIdx.y * 32 * W + ti;
    if (!last) {
        unsigned long long zp[16];
#pragma unroll
        for (int r2 = 0; r2 < 16; r2++) zp[r2] = pack2(z[2 * r2], z[2 * r2 + 1]);
        // this lane produces out channels [half16, half16+16): residual add
        // needs cur[c] which this lane holds in cp[]
#pragma unroll
        for (int cc = 0; cc < 16; cc++) {
            int c = half16 + cc;
            const ulonglong2* rv = (const ulonglong2*)(sR + c * 32);
            unsigned long long o0 = 0, o1 = 0;
#pragma unroll
            for (int j = 0; j < 8; j++) {
                ulonglong2 w = rv[j];
                o0 = ffma2(w.x, zp[2 * j],     o0);
                o1 = ffma2(w.y, zp[2 * j + 1], o1);
            }
            float2 v0 = unpack2(o0), v1 = unpack2(o1);
            float2 pc = unpack2(cp[cc]);
            ob[c * W] = pc.y + (v0.x + v0.y) + (v1.x + v1.y);
        }
    } else {
#pragma unroll
        for (int cc = 0; cc < 16; cc++)
            ob[(half16 + cc) * W] = z[half16 + cc];
    }
}

// ---------------------------------------------------------------------------
// Head1: h[b,c,j] = relu(e1 @ relu(skip39 @ z) + b1), z at ti = 4096 + j.
// ---------------------------------------------------------------------------
__global__ __launch_bounds__(256) void head1_kernel(
    const float* __restrict__ skip39, const float* __restrict__ e1,
    const float* __restrict__ b1)
{
    __shared__ __align__(16) float zt[32 * 32];
    __shared__ __align__(16) float s_sm[256 * 32];

    const int b  = blockIdx.y;
    const int j0 = blockIdx.x * 32;
    const int tid = threadIdx.x;
    const int p = tid & 31, g = tid >> 5;

    const float* zsrc = g_bufA + (size_t)b * 32 * W + 4096 + j0;
#pragma unroll
    for (int it = 0; it < 4; it++) {
        int r = it * 8 + g;
        zt[r * 32 + p] = zsrc[(size_t)r * W + p];
    }
    __syncthreads();

    float zr[32];
#pragma unroll
    for (int r = 0; r < 32; r++) zr[r] = zt[r * 32 + p];

#pragma unroll 4
    for (int cl = 0; cl < 32; cl++) {
        int c = g * 32 + cl;
        const float4* skv = (const float4*)(skip39 + c * 32);
        float a0 = 0.f, a1 = 0.f;
#pragma unroll
        for (int r4 = 0; r4 < 8; r4++) {
            float4 w = __ldg(&skv[r4]);
            a0 = fmaf(w.x, zr[4 * r4 + 0], a0);
            a1 = fmaf(w.y, zr[4 * r4 + 1], a1);
            a0 = fmaf(w.z, zr[4 * r4 + 2], a0);
            a1 = fmaf(w.w, zr[4 * r4 + 3], a1);
        }
        s_sm[c * 32 + p] = fmaxf(a0 + a1, 0.f);
    }
    __syncthreads();

    unsigned long long accp[16];
#pragma unroll
    for (int i = 0; i < 16; i++) accp[i] = 0ull;

    const float4* e1row = (const float4*)(e1 + tid * 256);
    for (int s4i = 0; s4i < 64; s4i++) {
        float4 w4 = __ldg(e1row + s4i);
        const float ws[4] = {w4.x, w4.y, w4.z, w4.w};
#pragma unroll
        for (int ss = 0; ss < 4; ss++) {
            unsigned long long wd = pack2(ws[ss], ws[ss]);
            const ulonglong2* sv = (const ulonglong2*)(s_sm + (s4i * 4 + ss) * 32);
#pragma unroll
            for (int q = 0; q < 8; q++) {
                ulonglong2 sx = sv[q];
                accp[2 * q]     = ffma2(wd, sx.x, accp[2 * q]);
                accp[2 * q + 1] = ffma2(wd, sx.y, accp[2 * q + 1]);
            }
        }
    }

    float bias = b1[tid];
    float* hb = g_h + ((size_t)b * 256 + tid) * 4096 + j0;
#pragma unroll
    for (int q = 0; q < 8; q++) {
        float2 u = unpack2(accp[2 * q]);
        float2 v = unpack2(accp[2 * q + 1]);
        float4 o;
        o.x = fmaxf(u.x + bias, 0.f);
        o.y = fmaxf(u.y + bias, 0.f);
        o.z = fmaxf(v.x + bias, 0.f);
        o.w = fmaxf(v.y + bias, 0.f);
        ((float4*)hb)[q] = o;
    }
}

// ---------------------------------------------------------------------------
// Head2: out[(b*4096+j)*256 + c] = e2 @ h + b2
// ---------------------------------------------------------------------------
__global__ __launch_bounds__(256) void head2_kernel(
    const float* __restrict__ e2, const float* __restrict__ b2,
    float* __restrict__ out)
{
    __shared__ __align__(16) float h_sm[256 * 32];

    const int b  = blockIdx.y;
    const int j0 = blockIdx.x * 32;
    const int tid = threadIdx.x;
    const int p = tid & 31, g = tid >> 5;

#pragma unroll 4
    for (int it = 0; it < 32; it++) {
        int s = it * 8 + g;
        h_sm[s * 32 + p] = g_h[((size_t)b * 256 + s) * 4096 + j0 + p];
    }
    __syncthreads();

    unsigned long long accp[16];
#pragma unroll
    for (int i = 0; i < 16; i++) accp[i] = 0ull;

    const float4* e2row = (const float4*)(e2 + tid * 256);
    for (int s4i = 0; s4i < 64; s4i++) {
        float4 w4 = __ldg(e2row + s4i);
        const float ws[4] = {w4.x, w4.y, w4.z, w4.w};
#pragma unroll
        for (int ss = 0; ss < 4; ss++) {
            unsigned long long wd = pack2(ws[ss], ws[ss]);
            const ulonglong2* hv = (const ulonglong2*)(h_sm + (s4i * 4 + ss) * 32);
#pragma unroll
            for (int q = 0; q < 8; q++) {
                ulonglong2 hx = hv[q];
                accp[2 * q]     = ffma2(wd, hx.x, accp[2 * q]);
                accp[2 * q + 1] = ffma2(wd, hx.y, accp[2 * q + 1]);
            }
        }
    }

    float bias = b2[tid];
    float* ob = out + ((size_t)b * 4096 + j0) * 256 + tid;
#pragma unroll
    for (int q = 0; q < 8; q++) {
        float2 u = unpack2(accp[2 * q]);
        float2 v = unpack2(accp[2 * q + 1]);
        ob[(size_t)(4 * q + 0) * 256] = u.x + bias;
        ob[(size_t)(4 * q + 1) * 256] = u.y + bias;
        ob[(size_t)(4 * q + 2) * 256] = v.x + bias;
        ob[(size_t)(4 * q + 3) * 256] = v.y + bias;
    }
}

// ---------------------------------------------------------------------------

extern "C" void kernel_launch(void* const* d_in, const int* in_sizes, int n_in,
                              void* d_out, int out_size)
{
    (void)in_sizes; (void)n_in; (void)out_size;
    const float* x_input    = (const float*)d_in[0];
    const float* start_w    = (const float*)d_in[1];
    const float* filter_w   = (const float*)d_in[2];
    const float* gate_w     = (const float*)d_in[3];
    const float* residual_w = (const float*)d_in[4];
    const float* skip_w     = (const float*)d_in[5];
    const float* e1         = (const float*)d_in[6];
    const float* b1         = (const float*)d_in[7];
    const float* e2         = (const float*)d_in[8];
    const float* b2         = (const float*)d_in[9];
    float* out = (float*)d_out;

    // dilations: 4 blocks of 1,2,4,...,512
    int ds[40];
    {
        int idx = 0;
        for (int blk = 0; blk < 4; blk++) {
            int nd = 1;
            for (int l = 0; l < 10; l++) { ds[idx++] = nd; nd *= 2; }
        }
    }
    // S[i] = 4096 - sum_{j>i} ds[j]  (valid output start for layer i)
    int S[40];
    {
        int suf = 0;
        for (int i = 39; i >= 0; i--) { S[i] = 4096 - suf; suf += ds[i]; }
    }

    start_kernel<<<dim3(32, 8), 128>>>(x_input, start_w);

    for (int i = 0; i < 40; i++) {
        int tstart = S[i];
        int n = W - tstart;
        int gx = (n + 63) / 64;
        layer_kernel<<<dim3(gx, 8), 128>>>(
            filter_w + (size_t)i * 2048, gate_w + (size_t)i * 2048,
            residual_w + (size_t)i * 1024,
            ds[i], tstart, i & 1, (i == 39) ? 1 : 0);
    }

    head1_kernel<<<dim3(128, 8), 256>>>(skip_w + (size_t)39 * 256 * 32, e1, b1);
    head2_kernel<<<dim3(128, 8), 256>>>(e2, b2, out);
}

// round 10
// speedup vs baseline: 1.3581x; 1.3581x over previous
#include <cuda_runtime.h>

#define W 8192

static __device__ __align__(16) float g_bufA[8 * 32 * W];
static __device__ __align__(16) float g_bufB[8 * 32 * W];
static __device__ __align__(16) float g_h[8 * 256 * 4096];

// ---- packed f32x2 helpers (sm_103a FFMA2 path) ----------------------------
__device__ __forceinline__ unsigned long long ffma2(
    unsigned long long a, unsigned long long b, unsigned long long c)
{
    unsigned long long d;
    asm("fma.rn.f32x2 %0, %1, %2, %3;" : "=l"(d) : "l"(a), "l"(b), "l"(c));
    return d;
}
__device__ __forceinline__ unsigned long long pack2(float lo, float hi)
{
    unsigned long long r;
    asm("mov.b64 %0, {%1, %2};" : "=l"(r) : "f"(lo), "f"(hi));
    return r;
}
__device__ __forceinline__ float2 unpack2(unsigned long long v)
{
    float2 r;
    asm("mov.b64 {%0, %1}, %2;" : "=f"(r.x), "=f"(r.y) : "l"(v));
    return r;
}

// ---------------------------------------------------------------------------
// Start conv: bufA[b,c,ti] = sum_k start_w[c,k] * x_input[b,k,8192+ti]
// ---------------------------------------------------------------------------
__global__ __launch_bounds__(128) void start_kernel(
    const float* __restrict__ x_input, const float* __restrict__ start_w)
{
    __shared__ __align__(16) float wsm[32 * 256];  // [c][k]
    const int b = blockIdx.y;
    for (int i = threadIdx.x; i < 32 * 256; i += 128) wsm[i] = start_w[i];
    __syncthreads();

    const int ti = (blockIdx.x * 128 + threadIdx.x) * 2;
    const float* xb = x_input + (size_t)b * 256 * 16384 + 8192 + ti;

    float2 acc[32];
#pragma unroll
    for (int c = 0; c < 32; c++) acc[c] = make_float2(0.f, 0.f);

    const float4* wv = (const float4*)wsm;
#pragma unroll 4
    for (int k4 = 0; k4 < 64; k4++) {
        float2 x0 = *(const float2*)(xb + (size_t)(k4 * 4 + 0) * 16384);
        float2 x1 = *(const float2*)(xb + (size_t)(k4 * 4 + 1) * 16384);
        float2 x2 = *(const float2*)(xb + (size_t)(k4 * 4 + 2) * 16384);
        float2 x3 = *(const float2*)(xb + (size_t)(k4 * 4 + 3) * 16384);
#pragma unroll
        for (int c = 0; c < 32; c++) {
            float4 w = wv[c * 64 + k4];
            acc[c].x = fmaf(w.x, x0.x, acc[c].x);
            acc[c].y = fmaf(w.x, x0.y, acc[c].y);
            acc[c].x = fmaf(w.y, x1.x, acc[c].x);
            acc[c].y = fmaf(w.y, x1.y, acc[c].y);
            acc[c].x = fmaf(w.z, x2.x, acc[c].x);
            acc[c].y = fmaf(w.z, x2.y, acc[c].y);
            acc[c].x = fmaf(w.w, x3.x, acc[c].x);
            acc[c].y = fmaf(w.w, x3.y, acc[c].y);
        }
    }
#pragma unroll
    for (int c = 0; c < 32; c++)
        *(float2*)(&g_bufA[((size_t)b * 32 + c) * W + ti]) = acc[c];
}

// ---------------------------------------------------------------------------
// Layer kernel, 1 thread/position (R8 version, for early/large layers).
// ---------------------------------------------------------------------------
__global__ __launch_bounds__(128, 4) void layer_kernel(
    const float* __restrict__ filt, const float* __restrict__ gate,
    const float* __restrict__ resid, int d, int tstart, int dir, int last)
{
    __shared__ __align__(16) float sF[2048], sG[2048], sR[1024];
    {
        const float4* f4 = (const float4*)filt;
        const float4* g4 = (const float4*)gate;
        const float4* r4 = (const float4*)resid;
        float4* sF4 = (float4*)sF;
        float4* sG4 = (float4*)sG;
        float4* sR4 = (float4*)sR;
        for (int i = threadIdx.x; i < 512; i += 128) { sF4[i] = f4[i]; sG4[i] = g4[i]; }
        for (int i = threadIdx.x; i < 256; i += 128) sR4[i] = r4[i];
    }
    __syncthreads();

    const float* xin  = dir ? g_bufB : g_bufA;
    float*       xout = dir ? g_bufA : g_bufB;

    int ti = tstart + blockIdx.x * 128 + threadIdx.x;
    if (ti >= W) return;

    const float* xb = xin + (size_t)blockIdx.y * 32 * W + ti;

    unsigned long long cp[32];  // (prev, cur) packed per input channel
#pragma unroll
    for (int r = 0; r < 32; r++) {
        float c_ = xb[r * W];
        float p_ = xb[r * W - d];
        cp[r] = pack2(p_, c_);
    }

    float z[32];
#pragma unroll
    for (int c = 0; c < 32; c++) {
        const ulonglong2* fv = (const ulonglong2*)(sF + c * 64);
        const ulonglong2* gv = (const ulonglong2*)(sG + c * 64);
        unsigned long long af0 = 0, af1 = 0, ag0 = 0, ag1 = 0;
#pragma unroll
        for (int r2 = 0; r2 < 16; r2++) {
            ulonglong2 wf = fv[r2];
            ulonglong2 wg = gv[r2];
            af0 = ffma2(wf.x, cp[2 * r2],     af0);
            af1 = ffma2(wf.y, cp[2 * r2 + 1], af1);
            ag0 = ffma2(wg.x, cp[2 * r2],     ag0);
            ag1 = ffma2(wg.y, cp[2 * r2 + 1], ag1);
        }
        float2 a0 = unpack2(af0), a1 = unpack2(af1);
        float2 g0 = unpack2(ag0), g1 = unpack2(ag1);
        float a = (a0.x + a0.y) + (a1.x + a1.y);
        float g = (g0.x + g0.y) + (g1.x + g1.y);
        float e2a = __expf(2.f * a);
        float eng = __expf(-g);
        z[c] = __fdividef(e2a - 1.f, (e2a + 1.f) * (1.f + eng));
    }

    float* ob = xout + (size_t)blockIdx.y * 32 * W + ti;
    if (!last) {
        unsigned long long zp[16];
#pragma unroll
        for (int r2 = 0; r2 < 16; r2++) zp[r2] = pack2(z[2 * r2], z[2 * r2 + 1]);
#pragma unroll
        for (int c = 0; c < 32; c++) {
            const ulonglong2* rv = (const ulonglong2*)(sR + c * 32);
            unsigned long long o0 = 0, o1 = 0;
#pragma unroll
            for (int j = 0; j < 8; j++) {
                ulonglong2 w = rv[j];
                o0 = ffma2(w.x, zp[2 * j],     o0);
                o1 = ffma2(w.y, zp[2 * j + 1], o1);
            }
            float2 v0 = unpack2(o0), v1 = unpack2(o1);
            float2 cc = unpack2(cp[c]);
            ob[c * W] = cc.y + (v0.x + v0.y) + (v1.x + v1.y);
        }
    } else {
#pragma unroll
        for (int c = 0; c < 32; c++) ob[c * W] = z[c];
    }
}

// ---------------------------------------------------------------------------
// Layer kernel, 2 threads/position (lane-pair channel split; R9 version).
// Used only when its grid fits a single wave at 5 blocks/SM (late layers).
// ---------------------------------------------------------------------------
__global__ __launch_bounds__(128, 5) void layer_kernel_split(
    const float* __restrict__ filt, const float* __restrict__ gate,
    const float* __restrict__ resid, int d, int tstart, int dir, int last)
{
    __shared__ __align__(16) float sF[2048], sG[2048], sR[1024];
    {
        const float4* f4 = (const float4*)filt;
        const float4* g4 = (const float4*)gate;
        const float4* r4 = (const float4*)resid;
        float4* sF4 = (float4*)sF;
        float4* sG4 = (float4*)sG;
        float4* sR4 = (float4*)sR;
        for (int i = threadIdx.x; i < 512; i += 128) { sF4[i] = f4[i]; sG4[i] = g4[i]; }
        for (int i = threadIdx.x; i < 256; i += 128) sR4[i] = r4[i];
    }
    __syncthreads();

    const float* xin  = dir ? g_bufB : g_bufA;
    float*       xout = dir ? g_bufA : g_bufB;

    const int half   = threadIdx.x & 1;
    const int half16 = half << 4;
    int ti = tstart + blockIdx.x * 64 + (threadIdx.x >> 1);
    if (ti >= W) return;
    const unsigned mask = __activemask();

    const float* xb = xin + (size_t)blockIdx.y * 32 * W + ti;

    unsigned long long cp[16];
#pragma unroll
    for (int r = 0; r < 16; r++) {
        const float* xr = xb + (half16 + r) * W;
        cp[r] = pack2(xr[-d], xr[0]);
    }

    float z[32];
#pragma unroll
    for (int c = 0; c < 32; c++) {
        const ulonglong2* fv = (const ulonglong2*)(sF + c * 64 + half * 32);
        const ulonglong2* gv = (const ulonglong2*)(sG + c * 64 + half * 32);
        unsigned long long af0 = 0, af1 = 0, ag0 = 0, ag1 = 0;
#pragma unroll
        for (int j = 0; j < 8; j++) {
            ulonglong2 wf = fv[j];
            ulonglong2 wg = gv[j];
            af0 = ffma2(wf.x, cp[2 * j],     af0);
            af1 = ffma2(wf.y, cp[2 * j + 1], af1);
            ag0 = ffma2(wg.x, cp[2 * j],     ag0);
            ag1 = ffma2(wg.y, cp[2 * j + 1], ag1);
        }
        float2 a0 = unpack2(af0), a1 = unpack2(af1);
        float2 g0 = unpack2(ag0), g1 = unpack2(ag1);
        float pa = (a0.x + a0.y) + (a1.x + a1.y);
        float pg = (g0.x + g0.y) + (g1.x + g1.y);
        pa += __shfl_xor_sync(mask, pa, 1);
        pg += __shfl_xor_sync(mask, pg, 1);
        float e2a = __expf(2.f * pa);
        float eng = __expf(-pg);
        z[c] = __fdividef(e2a - 1.f, (e2a + 1.f) * (1.f + eng));
    }

    float* ob = xout + (size_t)blockIdx.y * 32 * W + ti;
    if (!last) {
        unsigned long long zp[16];
#pragma unroll
        for (int r2 = 0; r2 < 16; r2++) zp[r2] = pack2(z[2 * r2], z[2 * r2 + 1]);
#pragma unroll
        for (int cc = 0; cc < 16; cc++) {
            int c = half16 + cc;
            const ulonglong2* rv = (const ulonglong2*)(sR + c * 32);
            unsigned long long o0 = 0, o1 = 0;
#pragma unroll
            for (int j = 0; j < 8; j++) {
                ulonglong2 w = rv[j];
                o0 = ffma2(w.x, zp[2 * j],     o0);
                o1 = ffma2(w.y, zp[2 * j + 1], o1);
            }
            float2 v0 = unpack2(o0), v1 = unpack2(o1);
            float2 pc = unpack2(cp[cc]);
            ob[c * W] = pc.y + (v0.x + v0.y) + (v1.x + v1.y);
        }
    } else {
#pragma unroll
        for (int cc = 0; cc < 16; cc++)
            ob[(half16 + cc) * W] = z[half16 + cc];
    }
}

// ---------------------------------------------------------------------------
// Head1: h[b,c,j] = relu(e1 @ relu(skip39 @ z) + b1), z at ti = 4096 + j.
// ---------------------------------------------------------------------------
__global__ __launch_bounds__(256) void head1_kernel(
    const float* __restrict__ skip39, const float* __restrict__ e1,
    const float* __restrict__ b1)
{
    __shared__ __align__(16) float zt[32 * 32];
    __shared__ __align__(16) float s_sm[256 * 32];

    const int b  = blockIdx.y;
    const int j0 = blockIdx.x * 32;
    const int tid = threadIdx.x;
    const int p = tid & 31, g = tid >> 5;

    const float* zsrc = g_bufA + (size_t)b * 32 * W + 4096 + j0;
#pragma unroll
    for (int it = 0; it < 4; it++) {
        int r = it * 8 + g;
        zt[r * 32 + p] = zsrc[(size_t)r * W + p];
    }
    __syncthreads();

    float zr[32];
#pragma unroll
    for (int r = 0; r < 32; r++) zr[r] = zt[r * 32 + p];

#pragma unroll 4
    for (int cl = 0; cl < 32; cl++) {
        int c = g * 32 + cl;
        const float4* skv = (const float4*)(skip39 + c * 32);
        float a0 = 0.f, a1 = 0.f;
#pragma unroll
        for (int r4 = 0; r4 < 8; r4++) {
            float4 w = __ldg(&skv[r4]);
            a0 = fmaf(w.x, zr[4 * r4 + 0], a0);
            a1 = fmaf(w.y, zr[4 * r4 + 1], a1);
            a0 = fmaf(w.z, zr[4 * r4 + 2], a0);
            a1 = fmaf(w.w, zr[4 * r4 + 3], a1);
        }
        s_sm[c * 32 + p] = fmaxf(a0 + a1, 0.f);
    }
    __syncthreads();

    unsigned long long accp[16];
#pragma unroll
    for (int i = 0; i < 16; i++) accp[i] = 0ull;

    const float4* e1row = (const float4*)(e1 + tid * 256);
    for (int s4i = 0; s4i < 64; s4i++) {
        float4 w4 = __ldg(e1row + s4i);
        const float ws[4] = {w4.x, w4.y, w4.z, w4.w};
#pragma unroll
        for (int ss = 0; ss < 4; ss++) {
            unsigned long long wd = pack2(ws[ss], ws[ss]);
            const ulonglong2* sv = (const ulonglong2*)(s_sm + (s4i * 4 + ss) * 32);
#pragma unroll
            for (int q = 0; q < 8; q++) {
                ulonglong2 sx = sv[q];
                accp[2 * q]     = ffma2(wd, sx.x, accp[2 * q]);
                accp[2 * q + 1] = ffma2(wd, sx.y, accp[2 * q + 1]);
            }
        }
    }

    float bias = b1[tid];
    float* hb = g_h + ((size_t)b * 256 + tid) * 4096 + j0;
#pragma unroll
    for (int q = 0; q < 8; q++) {
        float2 u = unpack2(accp[2 * q]);
        float2 v = unpack2(accp[2 * q + 1]);
        float4 o;
        o.x = fmaxf(u.x + bias, 0.f);
        o.y = fmaxf(u.y + bias, 0.f);
        o.z = fmaxf(v.x + bias, 0.f);
        o.w = fmaxf(v.y + bias, 0.f);
        ((float4*)hb)[q] = o;
    }
}

// ---------------------------------------------------------------------------
// Head2: out[(b*4096+j)*256 + c] = e2 @ h + b2
// ---------------------------------------------------------------------------
__global__ __launch_bounds__(256) void head2_kernel(
    const float* __restrict__ e2, const float* __restrict__ b2,
    float* __restrict__ out)
{
    __shared__ __align__(16) float h_sm[256 * 32];

    const int b  = blockIdx.y;
    const int j0 = blockIdx.x * 32;
    const int tid = threadIdx.x;
    const int p = tid & 31, g = tid >> 5;

#pragma unroll 4
    for (int it = 0; it < 32; it++) {
        int s = it * 8 + g;
        h_sm[s * 32 + p] = g_h[((size_t)b * 256 + s) * 4096 + j0 + p];
    }
    __syncthreads();

    unsigned long long accp[16];
#pragma unroll
    for (int i = 0; i < 16; i++) accp[i] = 0ull;

    const float4* e2row = (const float4*)(e2 + tid * 256);
    for (int s4i = 0; s4i < 64; s4i++) {
        float4 w4 = __ldg(e2row + s4i);
        const float ws[4] = {w4.x, w4.y, w4.z, w4.w};
#pragma unroll
        for (int ss = 0; ss < 4; ss++) {
            unsigned long long wd = pack2(ws[ss], ws[ss]);
            const ulonglong2* hv = (const ulonglong2*)(h_sm + (s4i * 4 + ss) * 32);
#pragma unroll
            for (int q = 0; q < 8; q++) {
                ulonglong2 hx = hv[q];
                accp[2 * q]     = ffma2(wd, hx.x, accp[2 * q]);
                accp[2 * q + 1] = ffma2(wd, hx.y, accp[2 * q + 1]);
            }
        }
    }

    float bias = b2[tid];
    float* ob = out + ((size_t)b * 4096 + j0) * 256 + tid;
#pragma unroll
    for (int q = 0; q < 8; q++) {
        float2 u = unpack2(accp[2 * q]);
        float2 v = unpack2(accp[2 * q + 1]);
        ob[(size_t)(4 * q + 0) * 256] = u.x + bias;
        ob[(size_t)(4 * q + 1) * 256] = u.y + bias;
        ob[(size_t)(4 * q + 2) * 256] = v.x + bias;
        ob[(size_t)(4 * q + 3) * 256] = v.y + bias;
    }
}

// ---------------------------------------------------------------------------

extern "C" void kernel_launch(void* const* d_in, const int* in_sizes, int n_in,
                              void* d_out, int out_size)
{
    (void)in_sizes; (void)n_in; (void)out_size;
    const float* x_input    = (const float*)d_in[0];
    const float* start_w    = (const float*)d_in[1];
    const float* filter_w   = (const float*)d_in[2];
    const float* gate_w     = (const float*)d_in[3];
    const float* residual_w = (const float*)d_in[4];
    const float* skip_w     = (const float*)d_in[5];
    const float* e1         = (const float*)d_in[6];
    const float* b1         = (const float*)d_in[7];
    const float* e2         = (const float*)d_in[8];
    const float* b2         = (const float*)d_in[9];
    float* out = (float*)d_out;

    // dilations: 4 blocks of 1,2,4,...,512
    int ds[40];
    {
        int idx = 0;
        for (int blk = 0; blk < 4; blk++) {
            int nd = 1;
            for (int l = 0; l < 10; l++) { ds[idx++] = nd; nd *= 2; }
        }
    }
    // S[i] = 4096 - sum_{j>i} ds[j]  (valid output start for layer i)
    int S[40];
    {
        int suf = 0;
        for (int i = 39; i >= 0; i--) { S[i] = 4096 - suf; suf += ds[i]; }
    }

    start_kernel<<<dim3(32, 8), 128>>>(x_input, start_w);

    for (int i = 0; i < 40; i++) {
        int tstart = S[i];
        int n = W - tstart;
        // 2-thread/position split kernel only when its grid fits one wave
        // at 5 blocks/SM (148 SMs * 5 = 740; keep margin -> 736).
        int gx2 = (n + 63) / 64;
        if (gx2 * 8 <= 736) {
            layer_kernel_split<<<dim3(gx2, 8), 128>>>(
                filter_w + (size_t)i * 2048, gate_w + (size_t)i * 2048,
                residual_w + (size_t)i * 1024,
                ds[i], tstart, i & 1, (i == 39) ? 1 : 0);
        } else {
            int gx = (n + 127) / 128;
            layer_kernel<<<dim3(gx, 8), 128>>>(
                filter_w + (size_t)i * 2048, gate_w + (size_t)i * 2048,
                residual_w + (size_t)i * 1024,
                ds[i], tstart, i & 1, (i == 39) ? 1 : 0);
        }
    }

    head1_kernel<<<dim3(128, 8), 256>>>(skip_w + (size_t)39 * 256 * 32, e1, b1);
    head2_kernel<<<dim3(128, 8), 256>>>(e2, b2, out);
}

// round 11
// speedup vs baseline: 1.4671x; 1.0803x over previous
#include <cuda_runtime.h>

#define W 8192

static __device__ __align__(16) float g_bufA[8 * 32 * W];
static __device__ __align__(16) float g_bufB[8 * 32 * W];

// ---- packed f32x2 helpers (sm_103a FFMA2 path) ----------------------------
__device__ __forceinline__ unsigned long long ffma2(
    unsigned long long a, unsigned long long b, unsigned long long c)
{
    unsigned long long d;
    asm("fma.rn.f32x2 %0, %1, %2, %3;" : "=l"(d) : "l"(a), "l"(b), "l"(c));
    return d;
}
__device__ __forceinline__ unsigned long long pack2(float lo, float hi)
{
    unsigned long long r;
    asm("mov.b64 %0, {%1, %2};" : "=l"(r) : "f"(lo), "f"(hi));
    return r;
}
__device__ __forceinline__ float2 unpack2(unsigned long long v)
{
    float2 r;
    asm("mov.b64 {%0, %1}, %2;" : "=f"(r.x), "=f"(r.y) : "l"(v));
    return r;
}

// ---------------------------------------------------------------------------
// Start conv: bufA[b,c,ti] = sum_k start_w[c,k] * x_input[b,k,8192+ti]
// ---------------------------------------------------------------------------
__global__ __launch_bounds__(128) void start_kernel(
    const float* __restrict__ x_input, const float* __restrict__ start_w)
{
    __shared__ __align__(16) float wsm[32 * 256];  // [c][k]
    const int b = blockIdx.y;
    for (int i = threadIdx.x; i < 32 * 256; i += 128) wsm[i] = start_w[i];
    __syncthreads();

    const int ti = (blockIdx.x * 128 + threadIdx.x) * 2;
    const float* xb = x_input + (size_t)b * 256 * 16384 + 8192 + ti;

    float2 acc[32];
#pragma unroll
    for (int c = 0; c < 32; c++) acc[c] = make_float2(0.f, 0.f);

    const float4* wv = (const float4*)wsm;
#pragma unroll 4
    for (int k4 = 0; k4 < 64; k4++) {
        float2 x0 = *(const float2*)(xb + (size_t)(k4 * 4 + 0) * 16384);
        float2 x1 = *(const float2*)(xb + (size_t)(k4 * 4 + 1) * 16384);
        float2 x2 = *(const float2*)(xb + (size_t)(k4 * 4 + 2) * 16384);
        float2 x3 = *(const float2*)(xb + (size_t)(k4 * 4 + 3) * 16384);
#pragma unroll
        for (int c = 0; c < 32; c++) {
            float4 w = wv[c * 64 + k4];
            acc[c].x = fmaf(w.x, x0.x, acc[c].x);
            acc[c].y = fmaf(w.x, x0.y, acc[c].y);
            acc[c].x = fmaf(w.y, x1.x, acc[c].x);
            acc[c].y = fmaf(w.y, x1.y, acc[c].y);
            acc[c].x = fmaf(w.z, x2.x, acc[c].x);
            acc[c].y = fmaf(w.z, x2.y, acc[c].y);
            acc[c].x = fmaf(w.w, x3.x, acc[c].x);
            acc[c].y = fmaf(w.w, x3.y, acc[c].y);
        }
    }
#pragma unroll
    for (int c = 0; c < 32; c++)
        *(float2*)(&g_bufA[((size_t)b * 32 + c) * W + ti]) = acc[c];
}

// ---------------------------------------------------------------------------
// One WaveNet layer, 1 thread/position, f32x2-packed (verified R8 version).
// ---------------------------------------------------------------------------
__global__ __launch_bounds__(128, 4) void layer_kernel(
    const float* __restrict__ filt, const float* __restrict__ gate,
    const float* __restrict__ resid, int d, int tstart, int dir, int last)
{
    __shared__ __align__(16) float sF[2048], sG[2048], sR[1024];
    {
        const float4* f4 = (const float4*)filt;
        const float4* g4 = (const float4*)gate;
        const float4* r4 = (const float4*)resid;
        float4* sF4 = (float4*)sF;
        float4* sG4 = (float4*)sG;
        float4* sR4 = (float4*)sR;
        for (int i = threadIdx.x; i < 512; i += 128) { sF4[i] = f4[i]; sG4[i] = g4[i]; }
        for (int i = threadIdx.x; i < 256; i += 128) sR4[i] = r4[i];
    }
    __syncthreads();

    const float* xin  = dir ? g_bufB : g_bufA;
    float*       xout = dir ? g_bufA : g_bufB;

    int ti = tstart + blockIdx.x * 128 + threadIdx.x;
    if (ti >= W) return;

    const float* xb = xin + (size_t)blockIdx.y * 32 * W + ti;

    unsigned long long cp[32];  // (prev, cur) packed per input channel
#pragma unroll
    for (int r = 0; r < 32; r++) {
        float c_ = xb[r * W];
        float p_ = xb[r * W - d];
        cp[r] = pack2(p_, c_);
    }

    float z[32];
#pragma unroll
    for (int c = 0; c < 32; c++) {
        const ulonglong2* fv = (const ulonglong2*)(sF + c * 64);
        const ulonglong2* gv = (const ulonglong2*)(sG + c * 64);
        unsigned long long af0 = 0, af1 = 0, ag0 = 0, ag1 = 0;
#pragma unroll
        for (int r2 = 0; r2 < 16; r2++) {
            ulonglong2 wf = fv[r2];
            ulonglong2 wg = gv[r2];
            af0 = ffma2(wf.x, cp[2 * r2],     af0);
            af1 = ffma2(wf.y, cp[2 * r2 + 1], af1);
            ag0 = ffma2(wg.x, cp[2 * r2],     ag0);
            ag1 = ffma2(wg.y, cp[2 * r2 + 1], ag1);
        }
        float2 a0 = unpack2(af0), a1 = unpack2(af1);
        float2 g0 = unpack2(ag0), g1 = unpack2(ag1);
        float a = (a0.x + a0.y) + (a1.x + a1.y);
        float g = (g0.x + g0.y) + (g1.x + g1.y);
        float e2a = __expf(2.f * a);
        float eng = __expf(-g);
        z[c] = __fdividef(e2a - 1.f, (e2a + 1.f) * (1.f + eng));
    }

    float* ob = xout + (size_t)blockIdx.y * 32 * W + ti;
    if (!last) {
        unsigned long long zp[16];
#pragma unroll
        for (int r2 = 0; r2 < 16; r2++) zp[r2] = pack2(z[2 * r2], z[2 * r2 + 1]);
#pragma unroll
        for (int c = 0; c < 32; c++) {
            const ulonglong2* rv = (const ulonglong2*)(sR + c * 32);
            unsigned long long o0 = 0, o1 = 0;
#pragma unroll
            for (int j = 0; j < 8; j++) {
                ulonglong2 w = rv[j];
                o0 = ffma2(w.x, zp[2 * j],     o0);
                o1 = ffma2(w.y, zp[2 * j + 1], o1);
            }
            float2 v0 = unpack2(o0), v1 = unpack2(o1);
            float2 cc = unpack2(cp[c]);
            ob[c * W] = cc.y + (v0.x + v0.y) + (v1.x + v1.y);
        }
    } else {
#pragma unroll
        for (int c = 0; c < 32; c++) ob[c * W] = z[c];
    }
}

// ---------------------------------------------------------------------------
// Fused head: out = e2 @ relu(e1 @ relu(skip39 @ z) + b1) + b2
// One block = 32 positions x 256 channels. h kept in-block (regs -> smem),
// eliminating the g_h global round-trip and one launch.
// Static smem: zt 4KB + s_sm 32KB = 36KB (< 48KB static limit).
// ---------------------------------------------------------------------------
__global__ __launch_bounds__(256) void head_fused_kernel(
    const float* __restrict__ skip39, const float* __restrict__ e1,
    const float* __restrict__ b1, const float* __restrict__ e2,
    const float* __restrict__ b2, float* __restrict__ out)
{
    __shared__ __align__(16) float zt[32 * 32];
    __shared__ __align__(16) float s_sm[256 * 32];

    const int b  = blockIdx.y;
    const int j0 = blockIdx.x * 32;
    const int tid = threadIdx.x;
    const int p = tid & 31, g = tid >> 5;

    // ---- phase 1: load z tile, compute s = relu(skip39 @ z) ----
    const float* zsrc = g_bufA + (size_t)b * 32 * W + 4096 + j0;
#pragma unroll
    for (int it = 0; it < 4; it++) {
        int r = it * 8 + g;
        zt[r * 32 + p] = zsrc[(size_t)r * W + p];
    }
    __syncthreads();

    float zr[32];
#pragma unroll
    for (int r = 0; r < 32; r++) zr[r] = zt[r * 32 + p];

#pragma unroll 4
    for (int cl = 0; cl < 32; cl++) {
        int c = g * 32 + cl;
        const float4* skv = (const float4*)(skip39 + c * 32);
        float a0 = 0.f, a1 = 0.f;
#pragma unroll
        for (int r4 = 0; r4 < 8; r4++) {
            float4 w = __ldg(&skv[r4]);
            a0 = fmaf(w.x, zr[4 * r4 + 0], a0);
            a1 = fmaf(w.y, zr[4 * r4 + 1], a1);
            a0 = fmaf(w.z, zr[4 * r4 + 2], a0);
            a1 = fmaf(w.w, zr[4 * r4 + 3], a1);
        }
        s_sm[c * 32 + p] = fmaxf(a0 + a1, 0.f);
    }
    __syncthreads();

    // ---- phase 2: h[tid, 0..31] = relu(e1[tid,:] @ s + b1[tid]) ----
    unsigned long long accp[16];
#pragma unroll
    for (int i = 0; i < 16; i++) accp[i] = 0ull;

    const float4* e1row = (const float4*)(e1 + tid * 256);
    for (int s4i = 0; s4i < 64; s4i++) {
        float4 w4 = __ldg(e1row + s4i);
        const float ws[4] = {w4.x, w4.y, w4.z, w4.w};
#pragma unroll
        for (int ss = 0; ss < 4; ss++) {
            unsigned long long wd = pack2(ws[ss], ws[ss]);
            const ulonglong2* sv = (const ulonglong2*)(s_sm + (s4i * 4 + ss) * 32);
#pragma unroll
            for (int q = 0; q < 8; q++) {
                ulonglong2 sx = sv[q];
                accp[2 * q]     = ffma2(wd, sx.x, accp[2 * q]);
                accp[2 * q + 1] = ffma2(wd, sx.y, accp[2 * q + 1]);
            }
        }
    }

    float h[32];
    {
        float bias1 = b1[tid];
#pragma unroll
        for (int q = 0; q < 8; q++) {
            float2 u = unpack2(accp[2 * q]);
            float2 v = unpack2(accp[2 * q + 1]);
            h[4 * q + 0] = fmaxf(u.x + bias1, 0.f);
            h[4 * q + 1] = fmaxf(u.y + bias1, 0.f);
            h[4 * q + 2] = fmaxf(v.x + bias1, 0.f);
            h[4 * q + 3] = fmaxf(v.y + bias1, 0.f);
        }
    }

    // ---- swap h into s_sm (all phase-2 reads complete first) ----
    __syncthreads();
    {
        float4* dst = (float4*)(s_sm + tid * 32);
#pragma unroll
        for (int q = 0; q < 8; q++)
            dst[q] = make_float4(h[4 * q], h[4 * q + 1], h[4 * q + 2], h[4 * q + 3]);
    }
    __syncthreads();

    // ---- phase 3: out[., tid] = e2[tid,:] @ h + b2[tid] ----
#pragma unroll
    for (int i = 0; i < 16; i++) accp[i] = 0ull;

    const float4* e2row = (const float4*)(e2 + tid * 256);
    for (int s4i = 0; s4i < 64; s4i++) {
        float4 w4 = __ldg(e2row + s4i);
        const float ws[4] = {w4.x, w4.y, w4.z, w4.w};
#pragma unroll
        for (int ss = 0; ss < 4; ss++) {
            unsigned long long wd = pack2(ws[ss], ws[ss]);
            const ulonglong2* hv = (const ulonglong2*)(s_sm + (s4i * 4 + ss) * 32);
#pragma unroll
            for (int q = 0; q < 8; q++) {
                ulonglong2 hx = hv[q];
                accp[2 * q]     = ffma2(wd, hx.x, accp[2 * q]);
                accp[2 * q + 1] = ffma2(wd, hx.y, accp[2 * q + 1]);
            }
        }
    }

    float bias2 = b2[tid];
    float* ob = out + ((size_t)b * 4096 + j0) * 256 + tid;
#pragma unroll
    for (int q = 0; q < 8; q++) {
        float2 u = unpack2(accp[2 * q]);
        float2 v = unpack2(accp[2 * q + 1]);
        ob[(size_t)(4 * q + 0) * 256] = u.x + bias2;
        ob[(size_t)(4 * q + 1) * 256] = u.y + bias2;
        ob[(size_t)(4 * q + 2) * 256] = v.x + bias2;
        ob[(size_t)(4 * q + 3) * 256] = v.y + bias2;
    }
}

// ---------------------------------------------------------------------------

extern "C" void kernel_launch(void* const* d_in, const int* in_sizes, int n_in,
                              void* d_out, int out_size)
{
    (void)in_sizes; (void)n_in; (void)out_size;
    const float* x_input    = (const float*)d_in[0];
    const float* start_w    = (const float*)d_in[1];
    const float* filter_w   = (const float*)d_in[2];
    const float* gate_w     = (const float*)d_in[3];
    const float* residual_w = (const float*)d_in[4];
    const float* skip_w     = (const float*)d_in[5];
    const float* e1         = (const float*)d_in[6];
    const float* b1         = (const float*)d_in[7];
    const float* e2         = (const float*)d_in[8];
    const float* b2         = (const float*)d_in[9];
    float* out = (float*)d_out;

    // dilations: 4 blocks of 1,2,4,...,512
    int ds[40];
    {
        int idx = 0;
        for (int blk = 0; blk < 4; blk++) {
            int nd = 1;
            for (int l = 0; l < 10; l++) { ds[idx++] = nd; nd *= 2; }
        }
    }
    // S[i] = 4096 - sum_{j>i} ds[j]  (valid output start for layer i)
    int S[40];
    {
        int suf = 0;
        for (int i = 39; i >= 0; i--) { S[i] = 4096 - suf; suf += ds[i]; }
    }

    start_kernel<<<dim3(32, 8), 128>>>(x_input, start_w);

    for (int i = 0; i < 40; i++) {
        int tstart = S[i];
        int n = W - tstart;
        int gx = (n + 127) / 128;
        layer_kernel<<<dim3(gx, 8), 128>>>(
            filter_w + (size_t)i * 2048, gate_w + (size_t)i * 2048,
            residual_w + (size_t)i * 1024,
            ds[i], tstart, i & 1, (i == 39) ? 1 : 0);
    }

    head_fused_kernel<<<dim3(128, 8), 256>>>(
        skip_w + (size_t)39 * 256 * 32, e1, b1, e2, b2, out);
}

// round 12
// speedup vs baseline: 1.4770x; 1.0067x over previous
#include <cuda_runtime.h>

#define W 8192

static __device__ __align__(16) float g_bufA[8 * 32 * W];
static __device__ __align__(16) float g_bufB[8 * 32 * W];

// ---- packed f32x2 helpers (sm_103a FFMA2 path) ----------------------------
__device__ __forceinline__ unsigned long long ffma2(
    unsigned long long a, unsigned long long b, unsigned long long c)
{
    unsigned long long d;
    asm("fma.rn.f32x2 %0, %1, %2, %3;" : "=l"(d) : "l"(a), "l"(b), "l"(c));
    return d;
}
__device__ __forceinline__ unsigned long long pack2(float lo, float hi)
{
    unsigned long long r;
    asm("mov.b64 %0, {%1, %2};" : "=l"(r) : "f"(lo), "f"(hi));
    return r;
}
__device__ __forceinline__ float2 unpack2(unsigned long long v)
{
    float2 r;
    asm("mov.b64 {%0, %1}, %2;" : "=f"(r.x), "=f"(r.y) : "l"(v));
    return r;
}

// ---------------------------------------------------------------------------
// Start conv: bufA[b,c,ti] = sum_k start_w[c,k] * x_input[b,k,8192+ti]
// ---------------------------------------------------------------------------
__global__ __launch_bounds__(128) void start_kernel(
    const float* __restrict__ x_input, const float* __restrict__ start_w)
{
    __shared__ __align__(16) float wsm[32 * 256];  // [c][k]
    const int b = blockIdx.y;
    for (int i = threadIdx.x; i < 32 * 256; i += 128) wsm[i] = start_w[i];
    __syncthreads();

    const int ti = (blockIdx.x * 128 + threadIdx.x) * 2;
    const float* xb = x_input + (size_t)b * 256 * 16384 + 8192 + ti;

    float2 acc[32];
#pragma unroll
    for (int c = 0; c < 32; c++) acc[c] = make_float2(0.f, 0.f);

    const float4* wv = (const float4*)wsm;
#pragma unroll 4
    for (int k4 = 0; k4 < 64; k4++) {
        float2 x0 = *(const float2*)(xb + (size_t)(k4 * 4 + 0) * 16384);
        float2 x1 = *(const float2*)(xb + (size_t)(k4 * 4 + 1) * 16384);
        float2 x2 = *(const float2*)(xb + (size_t)(k4 * 4 + 2) * 16384);
        float2 x3 = *(const float2*)(xb + (size_t)(k4 * 4 + 3) * 16384);
#pragma unroll
        for (int c = 0; c < 32; c++) {
            float4 w = wv[c * 64 + k4];
            acc[c].x = fmaf(w.x, x0.x, acc[c].x);
            acc[c].y = fmaf(w.x, x0.y, acc[c].y);
            acc[c].x = fmaf(w.y, x1.x, acc[c].x);
            acc[c].y = fmaf(w.y, x1.y, acc[c].y);
            acc[c].x = fmaf(w.z, x2.x, acc[c].x);
            acc[c].y = fmaf(w.z, x2.y, acc[c].y);
            acc[c].x = fmaf(w.w, x3.x, acc[c].x);
            acc[c].y = fmaf(w.w, x3.y, acc[c].y);
        }
    }
#pragma unroll
    for (int c = 0; c < 32; c++)
        *(float2*)(&g_bufA[((size_t)b * 32 + c) * W + ti]) = acc[c];
}

// ---------------------------------------------------------------------------
// WaveNet layer, warp-pair channel split: block = 64 positions x 2 halves.
// Warps 0-1: in-channels 0-15; warps 2-3: in-channels 16-31 (same positions).
// All LDG fully coalesced (consecutive positions per warp). Partial gated
// sums + z exchanged via conflict-free smem ([c][pos] layout).
// smem: weights 20KB + exch 16KB + zsh 8KB = 44KB -> 5 blocks/SM, 20 warps.
// ---------------------------------------------------------------------------
__global__ __launch_bounds__(128, 5) void layer_kernel(
    const float* __restrict__ filt, const float* __restrict__ gate,
    const float* __restrict__ resid, int d, int tstart, int dir, int last)
{
    __shared__ __align__(16) float sF[2048], sG[2048], sR[1024];
    __shared__ __align__(16) float exch[32 * 2 * 64];  // [c][pa|pg][pos]
    __shared__ __align__(16) float zsh[32 * 64];       // [c][pos]
    {
        const float4* f4 = (const float4*)filt;
        const float4* g4 = (const float4*)gate;
        const float4* r4 = (const float4*)resid;
        float4* sF4 = (float4*)sF;
        float4* sG4 = (float4*)sG;
        float4* sR4 = (float4*)sR;
        for (int i = threadIdx.x; i < 512; i += 128) { sF4[i] = f4[i]; sG4[i] = g4[i]; }
        for (int i = threadIdx.x; i < 256; i += 128) sR4[i] = r4[i];
    }
    __syncthreads();

    const float* xin  = dir ? g_bufB : g_bufA;
    float*       xout = dir ? g_bufA : g_bufB;

    const int pos = threadIdx.x & 63;
    const int h   = threadIdx.x >> 6;   // which channel half this thread owns
    const int hc  = h << 4;             // own channel base (in and out)

    int ti = tstart + blockIdx.x * 64 + pos;
    const bool valid = (ti < W);
    if (!valid) ti = W - 1;             // clamp; all stores to gmem guarded

    const float* xb = xin + (size_t)blockIdx.y * 32 * W + ti;

    // (prev, cur) for this half's 16 input channels — coalesced loads
    unsigned long long cp[16];
#pragma unroll
    for (int r = 0; r < 16; r++) {
        const float* xr = xb + (hc + r) * W;
        cp[r] = pack2(xr[-d], xr[0]);
    }

    const int oc_other = 16 - hc;       // other half's out-channel base

    // partials for the OTHER half's out channels -> smem
#pragma unroll
    for (int cl = 0; cl < 16; cl++) {
        const int c = oc_other + cl;
        const ulonglong2* fv = (const ulonglong2*)(sF + c * 64 + hc * 2);
        const ulonglong2* gv = (const ulonglong2*)(sG + c * 64 + hc * 2);
        unsigned long long af0 = 0, af1 = 0, ag0 = 0, ag1 = 0;
#pragma unroll
        for (int j = 0; j < 8; j++) {
            ulonglong2 wf = fv[j];
            ulonglong2 wg = gv[j];
            af0 = ffma2(wf.x, cp[2 * j],     af0);
            af1 = ffma2(wf.y, cp[2 * j + 1], af1);
            ag0 = ffma2(wg.x, cp[2 * j],     ag0);
            ag1 = ffma2(wg.y, cp[2 * j + 1], ag1);
        }
        float2 a0 = unpack2(af0), a1 = unpack2(af1);
        float2 b0 = unpack2(ag0), b1 = unpack2(ag1);
        exch[(c * 2 + 0) * 64 + pos] = (a0.x + a0.y) + (a1.x + a1.y);
        exch[(c * 2 + 1) * 64 + pos] = (b0.x + b0.y) + (b1.x + b1.y);
    }

    // partials for OWN out channels -> registers
    float pao[16], pgo[16];
#pragma unroll
    for (int cl = 0; cl < 16; cl++) {
        const int c = hc + cl;
        const ulonglong2* fv = (const ulonglong2*)(sF + c * 64 + hc * 2);
        const ulonglong2* gv = (const ulonglong2*)(sG + c * 64 + hc * 2);
        unsigned long long af0 = 0, af1 = 0, ag0 = 0, ag1 = 0;
#pragma unroll
        for (int j = 0; j < 8; j++) {
            ulonglong2 wf = fv[j];
            ulonglong2 wg = gv[j];
            af0 = ffma2(wf.x, cp[2 * j],     af0);
            af1 = ffma2(wf.y, cp[2 * j + 1], af1);
            ag0 = ffma2(wg.x, cp[2 * j],     ag0);
            ag1 = ffma2(wg.y, cp[2 * j + 1], ag1);
        }
        float2 a0 = unpack2(af0), a1 = unpack2(af1);
        float2 b0 = unpack2(ag0), b1 = unpack2(ag1);
        pao[cl] = (a0.x + a0.y) + (a1.x + a1.y);
        pgo[cl] = (b0.x + b0.y) + (b1.x + b1.y);
    }
    __syncthreads();

    // combine partials, activate: z for OWN 16 out channels
    float z[16];
#pragma unroll
    for (int cl = 0; cl < 16; cl++) {
        const int c = hc + cl;
        float pa = pao[cl] + exch[(c * 2 + 0) * 64 + pos];
        float pg = pgo[cl] + exch[(c * 2 + 1) * 64 + pos];
        float e2a = __expf(2.f * pa);
        float eng = __expf(-pg);
        z[cl] = __fdividef(e2a - 1.f, (e2a + 1.f) * (1.f + eng));
    }

    float* ob = xout + (size_t)blockIdx.y * 32 * W + ti;
    if (last) {               // uniform branch across the whole block
        if (valid) {
#pragma unroll
            for (int cl = 0; cl < 16; cl++) ob[(hc + cl) * W] = z[cl];
        }
        return;
    }

    // share z so both halves see all 32 channels
#pragma unroll
    for (int cl = 0; cl < 16; cl++) zsh[(hc + cl) * 64 + pos] = z[cl];
    __syncthreads();

    unsigned long long zp[16];
#pragma unroll
    for (int r2 = 0; r2 < 16; r2++)
        zp[r2] = pack2(zsh[(2 * r2) * 64 + pos], zsh[(2 * r2 + 1) * 64 + pos]);

    // residual conv: OWN 16 out channels (cur[c] held in cp[])
#pragma unroll
    for (int cl = 0; cl < 16; cl++) {
        const int c = hc + cl;
        const ulonglong2* rv = (const ulonglong2*)(sR + c * 32);
        unsigned long long o0 = 0, o1 = 0;
#pragma unroll
        for (int j = 0; j < 8; j++) {
            ulonglong2 w = rv[j];
            o0 = ffma2(w.x, zp[2 * j],     o0);
            o1 = ffma2(w.y, zp[2 * j + 1], o1);
        }
        float2 v0 = unpack2(o0), v1 = unpack2(o1);
        float2 pc = unpack2(cp[cl]);
        if (valid) ob[c * W] = pc.y + (v0.x + v0.y) + (v1.x + v1.y);
    }
}

// ---------------------------------------------------------------------------
// Fused head: out = e2 @ relu(e1 @ relu(skip39 @ z) + b1) + b2
// (verified R11 version, unchanged)
// ---------------------------------------------------------------------------
__global__ __launch_bounds__(256) void head_fused_kernel(
    const float* __restrict__ skip39, const float* __restrict__ e1,
    const float* __restrict__ b1, const float* __restrict__ e2,
    const float* __restrict__ b2, float* __restrict__ out)
{
    __shared__ __align__(16) float zt[32 * 32];
    __shared__ __align__(16) float s_sm[256 * 32];

    const int b  = blockIdx.y;
    const int j0 = blockIdx.x * 32;
    const int tid = threadIdx.x;
    const int p = tid & 31, g = tid >> 5;

    const float* zsrc = g_bufA + (size_t)b * 32 * W + 4096 + j0;
#pragma unroll
    for (int it = 0; it < 4; it++) {
        int r = it * 8 + g;
        zt[r * 32 + p] = zsrc[(size_t)r * W + p];
    }
    __syncthreads();

    float zr[32];
#pragma unroll
    for (int r = 0; r < 32; r++) zr[r] = zt[r * 32 + p];

#pragma unroll 4
    for (int cl = 0; cl < 32; cl++) {
        int c = g * 32 + cl;
        const float4* skv = (const float4*)(skip39 + c * 32);
        float a0 = 0.f, a1 = 0.f;
#pragma unroll
        for (int r4 = 0; r4 < 8; r4++) {
            float4 w = __ldg(&skv[r4]);
            a0 = fmaf(w.x, zr[4 * r4 + 0], a0);
            a1 = fmaf(w.y, zr[4 * r4 + 1], a1);
            a0 = fmaf(w.z, zr[4 * r4 + 2], a0);
            a1 = fmaf(w.w, zr[4 * r4 + 3], a1);
        }
        s_sm[c * 32 + p] = fmaxf(a0 + a1, 0.f);
    }
    __syncthreads();

    unsigned long long accp[16];
#pragma unroll
    for (int i = 0; i < 16; i++) accp[i] = 0ull;

    const float4* e1row = (const float4*)(e1 + tid * 256);
    for (int s4i = 0; s4i < 64; s4i++) {
        float4 w4 = __ldg(e1row + s4i);
        const float ws[4] = {w4.x, w4.y, w4.z, w4.w};
#pragma unroll
        for (int ss = 0; ss < 4; ss++) {
            unsigned long long wd = pack2(ws[ss], ws[ss]);
            const ulonglong2* sv = (const ulonglong2*)(s_sm + (s4i * 4 + ss) * 32);
#pragma unroll
            for (int q = 0; q < 8; q++) {
                ulonglong2 sx = sv[q];
                accp[2 * q]     = ffma2(wd, sx.x, accp[2 * q]);
                accp[2 * q + 1] = ffma2(wd, sx.y, accp[2 * q + 1]);
            }
        }
    }

    float h[32];
    {
        float bias1 = b1[tid];
#pragma unroll
        for (int q = 0; q < 8; q++) {
            float2 u = unpack2(accp[2 * q]);
            float2 v = unpack2(accp[2 * q + 1]);
            h[4 * q + 0] = fmaxf(u.x + bias1, 0.f);
            h[4 * q + 1] = fmaxf(u.y + bias1, 0.f);
            h[4 * q + 2] = fmaxf(v.x + bias1, 0.f);
            h[4 * q + 3] = fmaxf(v.y + bias1, 0.f);
        }
    }

    __syncthreads();
    {
        float4* dst = (float4*)(s_sm + tid * 32);
#pragma unroll
        for (int q = 0; q < 8; q++)
            dst[q] = make_float4(h[4 * q], h[4 * q + 1], h[4 * q + 2], h[4 * q + 3]);
    }
    __syncthreads();

#pragma unroll
    for (int i = 0; i < 16; i++) accp[i] = 0ull;

    const float4* e2row = (const float4*)(e2 + tid * 256);
    for (int s4i = 0; s4i < 64; s4i++) {
        float4 w4 = __ldg(e2row + s4i);
        const float ws[4] = {w4.x, w4.y, w4.z, w4.w};
#pragma unroll
        for (int ss = 0; ss < 4; ss++) {
            unsigned long long wd = pack2(ws[ss], ws[ss]);
            const ulonglong2* hv = (const ulonglong2*)(s_sm + (s4i * 4 + ss) * 32);
#pragma unroll
            for (int q = 0; q < 8; q++) {
                ulonglong2 hx = hv[q];
                accp[2 * q]     = ffma2(wd, hx.x, accp[2 * q]);
                accp[2 * q + 1] = ffma2(wd, hx.y, accp[2 * q + 1]);
            }
        }
    }

    float bias2 = b2[tid];
    float* ob = out + ((size_t)b * 4096 + j0) * 256 + tid;
#pragma unroll
    for (int q = 0; q < 8; q++) {
        float2 u = unpack2(accp[2 * q]);
        float2 v = unpack2(accp[2 * q + 1]);
        ob[(size_t)(4 * q + 0) * 256] = u.x + bias2;
        ob[(size_t)(4 * q + 1) * 256] = u.y + bias2;
        ob[(size_t)(4 * q + 2) * 256] = v.x + bias2;
        ob[(size_t)(4 * q + 3) * 256] = v.y + bias2;
    }
}

// ---------------------------------------------------------------------------

extern "C" void kernel_launch(void* const* d_in, const int* in_sizes, int n_in,
                              void* d_out, int out_size)
{
    (void)in_sizes; (void)n_in; (void)out_size;
    const float* x_input    = (const float*)d_in[0];
    const float* start_w    = (const float*)d_in[1];
    const float* filter_w   = (const float*)d_in[2];
    const float* gate_w     = (const float*)d_in[3];
    const float* residual_w = (const float*)d_in[4];
    const float* skip_w     = (const float*)d_in[5];
    const float* e1         = (const float*)d_in[6];
    const float* b1         = (const float*)d_in[7];
    const float* e2         = (const float*)d_in[8];
    const float* b2         = (const float*)d_in[9];
    float* out = (float*)d_out;

    // dilations: 4 blocks of 1,2,4,...,512
    int ds[40];
    {
        int idx = 0;
        for (int blk = 0; blk < 4; blk++) {
            int nd = 1;
            for (int l = 0; l < 10; l++) { ds[idx++] = nd; nd *= 2; }
        }
    }
    // S[i] = 4096 - sum_{j>i} ds[j]  (valid output start for layer i)
    int S[40];
    {
        int suf = 0;
        for (int i = 39; i >= 0; i--) { S[i] = 4096 - suf; suf += ds[i]; }
    }

    start_kernel<<<dim3(32, 8), 128>>>(x_input, start_w);

    for (int i = 0; i < 40; i++) {
        int tstart = S[i];
        int n = W - tstart;
        int gx = (n + 63) / 64;
        layer_kernel<<<dim3(gx, 8), 128>>>(
            filter_w + (size_t)i * 2048, gate_w + (size_t)i * 2048,
            residual_w + (size_t)i * 1024,
            ds[i], tstart, i & 1, (i == 39) ? 1 : 0);
    }

    head_fused_kernel<<<dim3(128, 8), 256>>>(
        skip_w + (size_t)39 * 256 * 32, e1, b1, e2, b2, out);
}